// round 16
// baseline (speedup 1.0000x reference)
#include <cuda_runtime.h>
#include <cuda_bf16.h>
#include <math.h>
#include <stdint.h>

#define BSZ 2
#define SEQ 1024
#define DM  2048
#define NH  32
#define NKV 8
#define HD  64
#define KVD 512

typedef __nv_bfloat16 bf16;

static const size_t OUT_ELEMS  = (size_t)BSZ * SEQ * DM;
static const size_t ATTN_ELEMS = (size_t)BSZ * NH * SEQ * SEQ;

// ---------------- device scratch (allocation-free rule) ----------------
__device__ __align__(16) bf16 g_xqh[BSZ*SEQ*DM], g_xql[BSZ*SEQ*DM];
__device__ __align__(16) bf16 g_xkh[BSZ*SEQ*DM], g_xkl[BSZ*SEQ*DM];
__device__ __align__(16) bf16 g_xvh[BSZ*SEQ*DM], g_xvl[BSZ*SEQ*DM];
__device__ __align__(16) bf16 g_wqh[DM*DM],  g_wql[DM*DM];
__device__ __align__(16) bf16 g_wkh[KVD*DM], g_wkl[KVD*DM];
__device__ __align__(16) bf16 g_wvh[KVD*DM], g_wvl[KVD*DM];
__device__ __align__(16) bf16 g_woh[DM*DM],  g_wol[DM*DM];
__device__ __align__(16) bf16 g_Qph[BSZ*SEQ*DM],  g_Qpl[BSZ*SEQ*DM];
__device__ __align__(16) bf16 g_Kph[BSZ*SEQ*KVD], g_Kpl[BSZ*SEQ*KVD];
__device__ __align__(16) bf16 g_Vth[BSZ*KVD*SEQ], g_Vtl[BSZ*KVD*SEQ];
__device__ __align__(16) bf16 g_Oh[BSZ*SEQ*DM], g_Ol[BSZ*SEQ*DM];
__device__ __align__(16) bf16 g_Ath[(size_t)BSZ*NH*SEQ*SEQ];   // exp(S) hi
__device__ __align__(16) bf16 g_Atl[(size_t)BSZ*NH*SEQ*SEQ];   // exp(S) lo
__device__ __align__(16) float g_partial[BSZ*NH*8*SEQ];        // exp row sums per n-tile
__device__ __align__(16) float g_attn_fb[(size_t)BSZ*NH*SEQ*SEQ];

// ---------------- helpers ----------------
__device__ __forceinline__ uint32_t smem_u32(const void* p) {
    uint32_t a;
    asm("{ .reg .u64 t; cvta.to.shared.u64 t, %1; cvt.u32.u64 %0, t; }" : "=r"(a) : "l"(p));
    return a;
}
__device__ __forceinline__ void ldsm4(uint32_t* r, uint32_t addr) {
    asm volatile("ldmatrix.sync.aligned.m8n8.x4.shared.b16 {%0,%1,%2,%3}, [%4];"
                 : "=r"(r[0]), "=r"(r[1]), "=r"(r[2]), "=r"(r[3]) : "r"(addr));
}
__device__ __forceinline__ void mma16816(float* d, const uint32_t* a, uint32_t b0, uint32_t b1) {
    asm volatile("mma.sync.aligned.m16n8k16.row.col.f32.bf16.bf16.f32 "
                 "{%0,%1,%2,%3}, {%4,%5,%6,%7}, {%8,%9}, {%0,%1,%2,%3};"
                 : "+f"(d[0]), "+f"(d[1]), "+f"(d[2]), "+f"(d[3])
                 : "r"(a[0]), "r"(a[1]), "r"(a[2]), "r"(a[3]), "r"(b0), "r"(b1));
}
__device__ __forceinline__ void cpwait2() { asm volatile("cp.async.wait_group 2;" ::: "memory"); }
__device__ __forceinline__ void cpwait1() { asm volatile("cp.async.wait_group 1;" ::: "memory"); }
__device__ __forceinline__ void cpwait0() { asm volatile("cp.async.wait_group 0;" ::: "memory"); }
__device__ __forceinline__ void cpcommit() { asm volatile("cp.async.commit_group;" ::: "memory"); }

__device__ __forceinline__ void split2(float x0, float x1, uint32_t& H, uint32_t& L) {
    bf16 h0 = __float2bfloat16(x0), h1 = __float2bfloat16(x1);
    bf16 l0 = __float2bfloat16(x0 - __bfloat162float(h0));
    bf16 l1 = __float2bfloat16(x1 - __bfloat162float(h1));
    H = (uint32_t)__bfloat16_as_ushort(h0) | ((uint32_t)__bfloat16_as_ushort(h1) << 16);
    L = (uint32_t)__bfloat16_as_ushort(l0) | ((uint32_t)__bfloat16_as_ushort(l1) << 16);
}
// reconstruct fp32 from packed hi/lo bf16 pair (lane hi=0 -> low half)
__device__ __forceinline__ float unsplit1(uint32_t H, uint32_t L, int hi) {
    unsigned short hh = hi ? (unsigned short)(H >> 16) : (unsigned short)(H & 0xffff);
    unsigned short ll = hi ? (unsigned short)(L >> 16) : (unsigned short)(L & 0xffff);
    return __bfloat162float(__ushort_as_bfloat16(hh)) + __bfloat162float(__ushort_as_bfloat16(ll));
}

// slab: R rows x 32 bf16 (64B), smem row stride 80B (conflict-free ldmatrix)
template<int R>
__device__ __forceinline__ void load_slab(uint32_t sdst, const bf16* __restrict__ g,
                                          int lda, int k0, int tid) {
    const bf16* gk = g + k0;
#pragma unroll
    for (int c = tid; c < R * 4; c += 256) {
        const int row = c >> 2, ch = c & 3;
        uint64_t src = __cvta_generic_to_global(gk + (size_t)row * lda + ch * 8);
        asm volatile("cp.async.cg.shared.global [%0], [%1], 16;"
                     :: "r"(sdst + (uint32_t)(row * 80 + ch * 16)), "l"(src) : "memory");
    }
}

template<int NT>
__device__ __forceinline__ void load_stage(uint32_t st,
    const bf16* Ah, const bf16* Al, int lda,
    const bf16* Bh, const bf16* Bl, int ldb, int k0, int tid) {
    load_slab<128>(st,                 Ah, lda, k0, tid);
    load_slab<128>(st + 10240,         Al, lda, k0, tid);
    load_slab<NT >(st + 20480,         Bh, ldb, k0, tid);
    load_slab<NT >(st + 20480 + NT*80, Bl, ldb, k0, tid);
    cpcommit();
}

// ---------------- split-bf16 warp-MMA GEMM body ----------------
// MMA ordering: hi*hi sweep, hi*lo sweep, lo*hi sweep (no RAW chains).
// EXPC: epilogue stores split2(exp(x)) to Ch/Cl and accumulates rowsum.
template<int NT, bool TRANSC, bool EXPC>
__device__ __forceinline__ void gemm_body(
    const bf16* __restrict__ Ah, const bf16* __restrict__ Al, int lda,
    const bf16* __restrict__ Bh, const bf16* __restrict__ Bl, int ldb,
    int K, float alpha, const float* __restrict__ bias,
    float* __restrict__ Cf, int ldc,
    bf16* __restrict__ Ch, bf16* __restrict__ Cl, int ldcs,
    float* __restrict__ rowsum)
{
    constexpr int WM  = (NT == 128) ? 64 : 32;
    constexpr int MT  = WM / 16;
    constexpr int NWM = 128 / WM;
    constexpr uint32_t STAGE = 20480u + 2u * NT * 80u;

    extern __shared__ char dsm[];
    const uint32_t base = smem_u32(dsm);
    const int tid = threadIdx.x;
    const int wid = tid >> 5;
    const int l   = tid & 31;

    const int m_off = (wid % NWM) * WM;
    const int n_off = (wid / NWM) * 32;

    const int aRow = m_off + (l & 7) + ((l >> 3) & 1) * 8;
    const int aK   = (l >> 4);
    const int bRow = n_off + (l & 7) + ((l >> 4) & 1) * 8;
    const int bK   = (l >> 3) & 1;

    float acc[MT][4][4];
#pragma unroll
    for (int i = 0; i < MT; i++)
#pragma unroll
        for (int j = 0; j < 4; j++)
#pragma unroll
            for (int q = 0; q < 4; q++) acc[i][j][q] = 0.0f;

    const int nslab = K >> 5;
    load_stage<NT>(base, Ah, Al, lda, Bh, Bl, ldb, 0, tid);
    if (nslab > 1) load_stage<NT>(base + STAGE, Ah, Al, lda, Bh, Bl, ldb, 32, tid);

    for (int i = 0; i < nslab; i++) {
        if (i < nslab - 1) cpwait1(); else cpwait0();
        __syncthreads();
        const uint32_t st  = base + (uint32_t)(i & 1) * STAGE;
        const uint32_t sAh = st + (uint32_t)(aRow * 80 + aK * 16);
        const uint32_t sAl = sAh + 10240u;
        const uint32_t sBh = st + 20480u + (uint32_t)(bRow * 80 + bK * 16);
        const uint32_t sBl = sBh + (uint32_t)(NT * 80);

#pragma unroll
        for (int k16 = 0; k16 < 2; k16++) {
            uint32_t ahf[MT][4], alf[MT][4], bhf[2][4], blf[2][4];
#pragma unroll
            for (int mt = 0; mt < MT; mt++) {
                ldsm4(ahf[mt], sAh + (uint32_t)(mt * 1280 + k16 * 32));
                ldsm4(alf[mt], sAl + (uint32_t)(mt * 1280 + k16 * 32));
            }
#pragma unroll
            for (int p = 0; p < 2; p++) {
                ldsm4(bhf[p], sBh + (uint32_t)(p * 1280 + k16 * 32));
                ldsm4(blf[p], sBl + (uint32_t)(p * 1280 + k16 * 32));
            }
#pragma unroll
            for (int mt = 0; mt < MT; mt++)
#pragma unroll
                for (int nt = 0; nt < 4; nt++) {
                    const int p = nt >> 1, h = (nt & 1) * 2;
                    mma16816(acc[mt][nt], ahf[mt], bhf[p][h], bhf[p][h + 1]);
                }
#pragma unroll
            for (int mt = 0; mt < MT; mt++)
#pragma unroll
                for (int nt = 0; nt < 4; nt++) {
                    const int p = nt >> 1, h = (nt & 1) * 2;
                    mma16816(acc[mt][nt], ahf[mt], blf[p][h], blf[p][h + 1]);
                }
#pragma unroll
            for (int mt = 0; mt < MT; mt++)
#pragma unroll
                for (int nt = 0; nt < 4; nt++) {
                    const int p = nt >> 1, h = (nt & 1) * 2;
                    mma16816(acc[mt][nt], alf[mt], bhf[p][h], bhf[p][h + 1]);
                }
        }
        __syncthreads();
        if (i + 2 < nslab)
            load_stage<NT>(base + (uint32_t)(i & 1) * STAGE, Ah, Al, lda, Bh, Bl, ldb, (i + 2) << 5, tid);
    }

    // epilogue
    float rs[MT][2];
#pragma unroll
    for (int mt = 0; mt < MT; mt++) { rs[mt][0] = 0.0f; rs[mt][1] = 0.0f; }

#pragma unroll
    for (int mt = 0; mt < MT; mt++) {
#pragma unroll
        for (int nt = 0; nt < 4; nt++) {
            const int col = n_off + nt * 8 + 2 * (l & 3);
            const float b0 = bias ? bias[col]     : 0.0f;
            const float b1 = bias ? bias[col + 1] : 0.0f;
#pragma unroll
            for (int half = 0; half < 2; half++) {
                const int row = m_off + mt * 16 + (l >> 2) + half * 8;
                float x0 = acc[mt][nt][2 * half]     * alpha + b0;
                float x1 = acc[mt][nt][2 * half + 1] * alpha + b1;
                if (Cf) {
                    *reinterpret_cast<float2*>(Cf + (size_t)row * ldc + col) = make_float2(x0, x1);
                }
                if (Ch) {
                    if (TRANSC) {
                        bf16 h0 = __float2bfloat16(x0), h1 = __float2bfloat16(x1);
                        bf16 l0 = __float2bfloat16(x0 - __bfloat162float(h0));
                        bf16 l1 = __float2bfloat16(x1 - __bfloat162float(h1));
                        Ch[(size_t)col * ldcs + row]       = h0;
                        Ch[(size_t)(col + 1) * ldcs + row] = h1;
                        Cl[(size_t)col * ldcs + row]       = l0;
                        Cl[(size_t)(col + 1) * ldcs + row] = l1;
                    } else {
                        float y0 = x0, y1 = x1;
                        if (EXPC) {
                            y0 = __expf(x0); y1 = __expf(x1);
                            rs[mt][half] += y0 + y1;
                        }
                        uint32_t H, L;
                        split2(y0, y1, H, L);
                        *reinterpret_cast<uint32_t*>(Ch + (size_t)row * ldcs + col) = H;
                        *reinterpret_cast<uint32_t*>(Cl + (size_t)row * ldcs + col) = L;
                    }
                }
            }
        }
    }

    if (rowsum) {
        // reduce exp sums: quad shuffle -> smem [row][n-warp-group] -> global
        float* part = reinterpret_cast<float*>(dsm);   // stage area, free now
        const int wn = wid / NWM;                       // 0..3 column group
        __syncthreads();
#pragma unroll
        for (int mt = 0; mt < MT; mt++)
#pragma unroll
            for (int half = 0; half < 2; half++) {
                float s = rs[mt][half];
                s += __shfl_xor_sync(0xffffffffu, s, 1);
                s += __shfl_xor_sync(0xffffffffu, s, 2);
                if ((l & 3) == 0) {
                    const int row = m_off + mt * 16 + (l >> 2) + half * 8;
                    part[row * 4 + wn] = s;
                }
            }
        __syncthreads();
        if (tid < 128)
            rowsum[tid] = part[tid * 4] + part[tid * 4 + 1] + part[tid * 4 + 2] + part[tid * 4 + 3];
    }
}

// ---------------- fused QKV projection: one launch, 384 CTAs ----------------
__global__ __launch_bounds__(256) void k_qkv(
    const bf16* __restrict__ xqh, const bf16* __restrict__ xql,
    const bf16* __restrict__ xkh, const bf16* __restrict__ xkl,
    const bf16* __restrict__ xvh, const bf16* __restrict__ xvl,
    const bf16* __restrict__ wqh, const bf16* __restrict__ wql,
    const bf16* __restrict__ wkh, const bf16* __restrict__ wkl,
    const bf16* __restrict__ wvh, const bf16* __restrict__ wvl,
    const float* __restrict__ bq, const float* __restrict__ bk, const float* __restrict__ bv,
    bf16* __restrict__ Qph, bf16* __restrict__ Qpl,
    bf16* __restrict__ Kph, bf16* __restrict__ Kpl,
    bf16* __restrict__ Vth, bf16* __restrict__ Vtl)
{
    const int blk = blockIdx.x;
    if (blk < 256) {
        const size_t m0 = (size_t)(blk >> 4) * 128, n0 = (size_t)(blk & 15) * 128;
        gemm_body<128, false, false>(xqh + m0 * DM, xql + m0 * DM, DM,
                              wqh + n0 * DM, wql + n0 * DM, DM,
                              DM, 1.0f, bq + n0, nullptr, 0,
                              Qph + m0 * DM + n0, Qpl + m0 * DM + n0, DM, nullptr);
    } else if (blk < 320) {
        const int t = blk - 256;
        const size_t m0 = (size_t)(t >> 2) * 128, n0 = (size_t)(t & 3) * 128;
        gemm_body<128, false, false>(xkh + m0 * DM, xkl + m0 * DM, DM,
                              wkh + n0 * DM, wkl + n0 * DM, DM,
                              DM, 1.0f, bk + n0, nullptr, 0,
                              Kph + m0 * KVD + n0, Kpl + m0 * KVD + n0, KVD, nullptr);
    } else {
        const int t = blk - 320;
        const size_t m0 = (size_t)(t >> 2) * 128, n0 = (size_t)(t & 3) * 128;
        const int b = (int)(m0 >> 10), s0 = (int)(m0 & (SEQ - 1));
        const size_t co = ((size_t)b * KVD + n0) * SEQ + s0;
        gemm_body<128, true, false>(xvh + m0 * DM, xvl + m0 * DM, DM,
                             wvh + n0 * DM, wvl + n0 * DM, DM,
                             DM, 1.0f, bv + n0, nullptr, 0,
                             Vth + co, Vtl + co, SEQ, nullptr);
    }
}

// ---------------- output projection ----------------
__global__ __launch_bounds__(256) void k_gemm128(
    const bf16* __restrict__ Ah, const bf16* __restrict__ Al, int lda,
    const bf16* __restrict__ Bh, const bf16* __restrict__ Bl, int ldb,
    int K, float alpha, const float* __restrict__ bias,
    float* __restrict__ Cf, int ldc)
{
    const int m0 = blockIdx.y * 128, n0 = blockIdx.x * 128;
    gemm_body<128, false, false>(Ah + (size_t)m0 * lda, Al + (size_t)m0 * lda, lda,
                   Bh + (size_t)n0 * ldb, Bl + (size_t)n0 * ldb, ldb,
                   K, alpha, bias ? bias + n0 : nullptr,
                   Cf + (size_t)m0 * ldc + n0, ldc,
                   nullptr, nullptr, 0, nullptr);
}

// scores: writes exp(S) hi/lo bf16 + per-row exp partial sums (no fp32 S)
__global__ __launch_bounds__(256) void k_scores_tc(
    const bf16* __restrict__ Qh, const bf16* __restrict__ Ql,
    const bf16* __restrict__ Kh, const bf16* __restrict__ Kl,
    bf16* __restrict__ Ath, bf16* __restrict__ Atl, float* __restrict__ partial)
{
    const int z = blockIdx.z, b = z >> 5, h = z & 31, kv = h >> 2;
    const int m0 = blockIdx.y * 128, n0 = blockIdx.x * 128;
    const size_t ao = (size_t)b * SEQ * DM  + (size_t)m0 * DM  + h  * HD;
    const size_t bo = (size_t)b * SEQ * KVD + (size_t)n0 * KVD + kv * HD;
    const size_t to = (size_t)z * SEQ * SEQ + (size_t)m0 * SEQ + n0;
    gemm_body<128, false, true>(Qh + ao, Ql + ao, DM, Kh + bo, Kl + bo, KVD,
                   HD, 0.125f, nullptr,
                   nullptr, 0,
                   Ath + to, Atl + to, SEQ,
                   partial + ((size_t)z * 8 + blockIdx.x) * SEQ + m0);
}

// ---------------- PV: pure cp.async pipeline, 3-stage ----------------
// O = inv[row] * sum_k exp[row,k] * V[k,d]; also writes normalized attn fp32.
__global__ __launch_bounds__(256) void k_pv(
    float* __restrict__ attn, const float* __restrict__ partial,
    const bf16* __restrict__ Ath, const bf16* __restrict__ Atl,
    const bf16* __restrict__ Vth, const bf16* __restrict__ Vtl,
    bf16* __restrict__ Oh, bf16* __restrict__ Ol)
{
    constexpr int NSLAB = SEQ / 32;            // 32
    constexpr uint32_t STG = 30720u;           // Ah 10240 | Al 10240 | Bh 5120 | Bl 5120
    extern __shared__ char dsm[];
    __shared__ float inv[128];
    const uint32_t base = smem_u32(dsm);
    const int tid = threadIdx.x;
    const int wid = tid >> 5;
    const int l   = tid & 31;

    const int z = blockIdx.y, b = z >> 5, h = z & 31, kv = h >> 2;
    const int m0 = blockIdx.x * 128;
    float* A = attn + (size_t)z * SEQ * SEQ + (size_t)m0 * SEQ;
    const bf16* Ah = Ath + (size_t)z * SEQ * SEQ + (size_t)m0 * SEQ;
    const bf16* Al = Atl + (size_t)z * SEQ * SEQ + (size_t)m0 * SEQ;
    const bf16* Vh = Vth + ((size_t)b * KVD + kv * HD) * SEQ;
    const bf16* Vl = Vtl + ((size_t)b * KVD + kv * HD) * SEQ;

    if (tid < 128) {
        float s = 0.0f;
#pragma unroll
        for (int t = 0; t < 8; t++)
            s += partial[((size_t)z * 8 + t) * SEQ + m0 + tid];
        inv[tid] = 1.0f / s;
    }

    auto load = [&](int st3, int k0) {
        const uint32_t sb = base + (uint32_t)st3 * STG;
        load_slab<128>(sb,         Ah, SEQ, k0, tid);
        load_slab<128>(sb + 10240, Al, SEQ, k0, tid);
        load_slab<64 >(sb + 20480, Vh, SEQ, k0, tid);
        load_slab<64 >(sb + 25600, Vl, SEQ, k0, tid);
        cpcommit();
    };
    load(0, 0); load(1, 32); load(2, 64);

    const int m_off = (wid & 3) * 32;          // NWM=4
    const int n_off = (wid >> 2) * 32;
    const int aRow = m_off + (l & 7) + ((l >> 3) & 1) * 8;
    const int aK   = (l >> 4);
    const int bRow = n_off + (l & 7) + ((l >> 4) & 1) * 8;
    const int bK   = (l >> 3) & 1;

    float acc[2][4][4];
#pragma unroll
    for (int i = 0; i < 2; i++)
#pragma unroll
        for (int j = 0; j < 4; j++)
#pragma unroll
            for (int q = 0; q < 4; q++) acc[i][j][q] = 0.0f;

    int s3 = 0;  // i % 3
    for (int i = 0; i < NSLAB; i++) {
        if (i < NSLAB - 2) cpwait2(); else if (i < NSLAB - 1) cpwait1(); else cpwait0();
        __syncthreads();
        const uint32_t st  = base + (uint32_t)s3 * STG;
        const uint32_t sAh = st + (uint32_t)(aRow * 80 + aK * 16);
        const uint32_t sAl = sAh + 10240u;
        const uint32_t sBh = st + 20480u + (uint32_t)(bRow * 80 + bK * 16);
        const uint32_t sBl = sBh + 5120u;

#pragma unroll
        for (int k16 = 0; k16 < 2; k16++) {
            uint32_t ahf[2][4], alf[2][4], bhf[2][4], blf[2][4];
#pragma unroll
            for (int mt = 0; mt < 2; mt++) {
                ldsm4(ahf[mt], sAh + (uint32_t)(mt * 1280 + k16 * 32));
                ldsm4(alf[mt], sAl + (uint32_t)(mt * 1280 + k16 * 32));
            }
#pragma unroll
            for (int p = 0; p < 2; p++) {
                ldsm4(bhf[p], sBh + (uint32_t)(p * 1280 + k16 * 32));
                ldsm4(blf[p], sBl + (uint32_t)(p * 1280 + k16 * 32));
            }
#pragma unroll
            for (int mt = 0; mt < 2; mt++)
#pragma unroll
                for (int nt = 0; nt < 4; nt++) {
                    const int p = nt >> 1, hh = (nt & 1) * 2;
                    mma16816(acc[mt][nt], ahf[mt], bhf[p][hh], bhf[p][hh + 1]);
                }
#pragma unroll
            for (int mt = 0; mt < 2; mt++)
#pragma unroll
                for (int nt = 0; nt < 4; nt++) {
                    const int p = nt >> 1, hh = (nt & 1) * 2;
                    mma16816(acc[mt][nt], ahf[mt], blf[p][hh], blf[p][hh + 1]);
                }
#pragma unroll
            for (int mt = 0; mt < 2; mt++)
#pragma unroll
                for (int nt = 0; nt < 4; nt++) {
                    const int p = nt >> 1, hh = (nt & 1) * 2;
                    mma16816(acc[mt][nt], alf[mt], bhf[p][hh], bhf[p][hh + 1]);
                }
        }

        // normalized attn write for slab i from resident smem (h+l)*inv
        {
            const int k0 = i << 5;
            const char* ab = dsm + s3 * STG;
#pragma unroll
            for (int j = 0; j < 2; j++) {
                const int c = tid + 256 * j;            // 0..511
                const int row = c >> 2, ch = c & 3;
                const float iv = inv[row];
                uint4 Hv = *reinterpret_cast<const uint4*>(ab + row * 80 + ch * 16);
                uint4 Lv = *reinterpret_cast<const uint4*>(ab + 10240 + row * 80 + ch * 16);
                float4 o0, o1;
                o0.x = unsplit1(Hv.x, Lv.x, 0) * iv;
                o0.y = unsplit1(Hv.x, Lv.x, 1) * iv;
                o0.z = unsplit1(Hv.y, Lv.y, 0) * iv;
                o0.w = unsplit1(Hv.y, Lv.y, 1) * iv;
                o1.x = unsplit1(Hv.z, Lv.z, 0) * iv;
                o1.y = unsplit1(Hv.z, Lv.z, 1) * iv;
                o1.z = unsplit1(Hv.w, Lv.w, 0) * iv;
                o1.w = unsplit1(Hv.w, Lv.w, 1) * iv;
                float* dst = A + (size_t)row * SEQ + k0 + ch * 8;
                *reinterpret_cast<float4*>(dst)     = o0;
                *reinterpret_cast<float4*>(dst + 4) = o1;
            }
        }

        if (i + 3 < NSLAB) {
            __syncthreads();   // all reads of stage s3 complete before refill
            load(s3, (i + 3) << 5);
        }
        s3 = (s3 == 2) ? 0 : s3 + 1;
    }

    // epilogue: scale by inv[row], hi/lo split out
    bf16* OH = Oh + ((size_t)b * SEQ + m0) * DM + h * HD;
    bf16* OL = Ol + ((size_t)b * SEQ + m0) * DM + h * HD;
#pragma unroll
    for (int mt = 0; mt < 2; mt++) {
#pragma unroll
        for (int nt = 0; nt < 4; nt++) {
            const int col = n_off + nt * 8 + 2 * (l & 3);
#pragma unroll
            for (int half = 0; half < 2; half++) {
                const int row = m_off + mt * 16 + (l >> 2) + half * 8;
                const float iv = inv[row];
                uint32_t H, L;
                split2(acc[mt][nt][2 * half] * iv, acc[mt][nt][2 * half + 1] * iv, H, L);
                *reinterpret_cast<uint32_t*>(OH + (size_t)row * DM + col) = H;
                *reinterpret_cast<uint32_t*>(OL + (size_t)row * DM + col) = L;
            }
        }
    }
}

// ---------------- elementwise glue (single launch) ----------------
__device__ __forceinline__ void split_seg(const float* __restrict__ x,
                                          bf16* __restrict__ h, bf16* __restrict__ l, int i)
{
    float4 v = reinterpret_cast<const float4*>(x)[i];
    uint2 H, L;
    split2(v.x, v.y, H.x, L.x);
    split2(v.z, v.w, H.y, L.y);
    reinterpret_cast<uint2*>(h)[i] = H;
    reinterpret_cast<uint2*>(l)[i] = L;
}

__global__ __launch_bounds__(256) void k_split_all(
    const float* __restrict__ q, const float* __restrict__ k, const float* __restrict__ v,
    const float* __restrict__ wq, const float* __restrict__ wk,
    const float* __restrict__ wv, const float* __restrict__ wo,
    bf16* __restrict__ xqh, bf16* __restrict__ xql,
    bf16* __restrict__ xkh, bf16* __restrict__ xkl,
    bf16* __restrict__ xvh, bf16* __restrict__ xvl,
    bf16* __restrict__ wqh, bf16* __restrict__ wql,
    bf16* __restrict__ wkh, bf16* __restrict__ wkl,
    bf16* __restrict__ wvh, bf16* __restrict__ wvl,
    bf16* __restrict__ woh, bf16* __restrict__ wol)
{
    const int blk = blockIdx.x;  // 3*4096 + 4096 + 1024 + 1024 + 4096 = 22528
    if (blk < 4096)        split_seg(q,  xqh, xql, blk * 256 + threadIdx.x);
    else if (blk < 8192)   split_seg(k,  xkh, xkl, (blk - 4096) * 256 + threadIdx.x);
    else if (blk < 12288)  split_seg(v,  xvh, xvl, (blk - 8192) * 256 + threadIdx.x);
    else if (blk < 16384)  split_seg(wq, wqh, wql, (blk - 12288) * 256 + threadIdx.x);
    else if (blk < 17408)  split_seg(wk, wkh, wkl, (blk - 16384) * 256 + threadIdx.x);
    else if (blk < 18432)  split_seg(wv, wvh, wvl, (blk - 17408) * 256 + threadIdx.x);
    else                   split_seg(wo, woh, wol, (blk - 18432) * 256 + threadIdx.x);
}

// ---------------- host ----------------
extern "C" void kernel_launch(void* const* d_in, const int* in_sizes, int n_in,
                              void* d_out, int out_size)
{
    const float* query = (const float*)d_in[0];
    const float* key   = (const float*)d_in[1];
    const float* value = (const float*)d_in[2];
    const float* Wq = (const float*)d_in[3];
    const float* bq = (const float*)d_in[4];
    const float* Wk = (const float*)d_in[5];
    const float* bk = (const float*)d_in[6];
    const float* Wv = (const float*)d_in[7];
    const float* bv = (const float*)d_in[8];
    const float* Wo = (const float*)d_in[9];
    const float* bo = (const float*)d_in[10];
    float* out = (float*)d_out;

    bf16 *xqh,*xql,*xkh,*xkl,*xvh,*xvl;
    bf16 *wqh,*wql,*wkh,*wkl,*wvh,*wvl,*woh,*wol;
    bf16 *Qph,*Qpl,*Kph,*Kpl,*Vth,*Vtl,*Oh,*Ol,*Ath,*Atl;
    float *attn, *partial;
    cudaGetSymbolAddress((void**)&xqh, g_xqh); cudaGetSymbolAddress((void**)&xql, g_xql);
    cudaGetSymbolAddress((void**)&xkh, g_xkh); cudaGetSymbolAddress((void**)&xkl, g_xkl);
    cudaGetSymbolAddress((void**)&xvh, g_xvh); cudaGetSymbolAddress((void**)&xvl, g_xvl);
    cudaGetSymbolAddress((void**)&wqh, g_wqh); cudaGetSymbolAddress((void**)&wql, g_wql);
    cudaGetSymbolAddress((void**)&wkh, g_wkh); cudaGetSymbolAddress((void**)&wkl, g_wkl);
    cudaGetSymbolAddress((void**)&wvh, g_wvh); cudaGetSymbolAddress((void**)&wvl, g_wvl);
    cudaGetSymbolAddress((void**)&woh, g_woh); cudaGetSymbolAddress((void**)&wol, g_wol);
    cudaGetSymbolAddress((void**)&Qph, g_Qph); cudaGetSymbolAddress((void**)&Qpl, g_Qpl);
    cudaGetSymbolAddress((void**)&Kph, g_Kph); cudaGetSymbolAddress((void**)&Kpl, g_Kpl);
    cudaGetSymbolAddress((void**)&Vth, g_Vth); cudaGetSymbolAddress((void**)&Vtl, g_Vtl);
    cudaGetSymbolAddress((void**)&Oh,  g_Oh);  cudaGetSymbolAddress((void**)&Ol,  g_Ol);
    cudaGetSymbolAddress((void**)&Ath, g_Ath); cudaGetSymbolAddress((void**)&Atl, g_Atl);
    cudaGetSymbolAddress((void**)&partial, g_partial);
    if ((size_t)out_size >= OUT_ELEMS + ATTN_ELEMS) attn = out + OUT_ELEMS;
    else cudaGetSymbolAddress((void**)&attn, g_attn_fb);

    const int S128 = 2 * (20480 + 2 * 128 * 80);  // 81920
    const int SPV  = 3 * 30720;                   // 92160
    cudaFuncSetAttribute(k_qkv,       cudaFuncAttributeMaxDynamicSharedMemorySize, S128);
    cudaFuncSetAttribute(k_gemm128,   cudaFuncAttributeMaxDynamicSharedMemorySize, S128);
    cudaFuncSetAttribute(k_scores_tc, cudaFuncAttributeMaxDynamicSharedMemorySize, S128);
    cudaFuncSetAttribute(k_pv,        cudaFuncAttributeMaxDynamicSharedMemorySize, SPV);

    // 1: all splits
    k_split_all<<<22528, 256>>>(query, key, value, Wq, Wk, Wv, Wo,
                                xqh, xql, xkh, xkl, xvh, xvl,
                                wqh, wql, wkh, wkl, wvh, wvl, woh, wol);

    // 2: fused QKV projections (384 CTAs)
    k_qkv<<<384, 256, S128>>>(xqh, xql, xkh, xkl, xvh, xvl,
                              wqh, wql, wkh, wkl, wvh, wvl,
                              bq, bk, bv, Qph, Qpl, Kph, Kpl, Vth, Vtl);

    // 3: scores (exp(S) hi/lo bf16 + exp row partial sums)
    k_scores_tc<<<dim3(SEQ/128, SEQ/128, BSZ*NH), 256, S128>>>(Qph, Qpl, Kph, Kpl, Ath, Atl, partial);

    // 4: PV (pure cp.async GEMM + normalized attn write)
    k_pv<<<dim3(SEQ/128, BSZ*NH), 256, SPV>>>(attn, partial, Ath, Atl, Vth, Vtl, Oh, Ol);

    // 5: output projection
    k_gemm128<<<dim3(DM/128, (BSZ*SEQ)/128), 256, S128>>>(
        Oh, Ol, DM, woh, wol, DM, DM, 1.0f, bo, out, DM);
}